// round 10
// baseline (speedup 1.0000x reference)
#include <cuda_runtime.h>
#include <math.h>
#include <stdint.h>

// Shapes (fixed by reference)
#define NT    8192
#define HDIM  1024
#define FDIM  4096
#define NE    8
#define TOPK  2

#define BM 128
#define MAXPAIR (NT * TOPK + NE * BM)   // 17408
#define MTILES  (MAXPAIR / BM)          // 136

// ---- small (fallback, R9-proven) tiling: 128x128x16, 2 stages, 128 thr ----
#define S_BN 128
#define S_KC 16
#define S_ASTR 20
#define S_BSTR 136      // == 8 mod 32: B-read banks 8r+q all distinct (132 was 2-way!)
#define S_STAGE_FLOATS (BM * S_ASTR + S_KC * S_BSTR)   // 2560+2176 = 4736
#define S_ABYTES (BM * S_ASTR * 4)
#define S_STAGE_BYTES (S_STAGE_FLOATS * 4)             // 18944; x2 = 37888 < 48K

// ---- big tiling: 128x256x32, 4 stages, 256 thr, dynamic smem ----
#define B_BN 256
#define B_KC 32
#define B_ASTR 36       // bank 4q+r: all 32 distinct
#define B_BSTR 264      // == 8 mod 32: bank 8r+q all distinct
#define B_STAGE_FLOATS (BM * B_ASTR + B_KC * B_BSTR)   // 4608+8448 = 13056
#define B_ABYTES (BM * B_ASTR * 4)                     // 18432
#define B_STAGE_BYTES (B_STAGE_FLOATS * 4)             // 52224
#define SMEM_BIG (4 * B_STAGE_BYTES)                   // 208896

// ---------------------------------------------------------------------------
// Scratch (device symbols: referenced ONLY from device code — host-side
// symbol args were the R7/R8 silent-zeros bug via GB300 ATS)
// ---------------------------------------------------------------------------
__device__ int   g_counts[NE];
__device__ int   g_cursor[NE];
__device__ int   g_seg[NE + 1];
__device__ int   g_pair_token[MAXPAIR];
__device__ int   g_tok_e[NT * TOPK];
__device__ float g_tok_w[NT * TOPK];
__device__ int   g_tok_pair[NT * TOPK];
__device__ float g_zrow[HDIM];                     // never written: zeros
__device__ float g_hbuf[(size_t)MAXPAIR * FDIM];
__device__ float g_ybuf[(size_t)MAXPAIR * HDIM];

// ---------------------------------------------------------------------------
// PTX helpers (non-arch-specific)
// ---------------------------------------------------------------------------
__device__ __forceinline__ uint32_t smem_u32(const void* p) {
    uint32_t a;
    asm("{ .reg .u64 t; cvta.to.shared.u64 t, %1; cvt.u32.u64 %0, t; }"
        : "=r"(a) : "l"(p));
    return a;
}
__device__ __forceinline__ uint32_t f2tf(float x) {
    uint32_t u;
    asm("cvt.rna.tf32.f32 %0, %1;" : "=r"(u) : "f"(x));
    return u;
}
__device__ __forceinline__ void cp16(uint32_t s, const float* g) {
    asm volatile("cp.async.cg.shared.global [%0], [%1], 16;"
                 :: "r"(s), "l"(g) : "memory");
}
__device__ __forceinline__ void cp_commit() {
    asm volatile("cp.async.commit_group;" ::: "memory");
}
__device__ __forceinline__ void cp_wait2() {
    asm volatile("cp.async.wait_group 2;" ::: "memory");
}
__device__ __forceinline__ void cp_wait1() {
    asm volatile("cp.async.wait_group 1;" ::: "memory");
}
__device__ __forceinline__ void cp_wait0() {
    asm volatile("cp.async.wait_group 0;" ::: "memory");
}
__device__ __forceinline__ void mma_tf32(float* c, const uint32_t* a,
                                         const uint32_t* b) {
    asm volatile(
        "mma.sync.aligned.m16n8k8.row.col.f32.tf32.tf32.f32 "
        "{%0,%1,%2,%3}, {%4,%5,%6,%7}, {%8,%9}, {%0,%1,%2,%3};"
        : "+f"(c[0]), "+f"(c[1]), "+f"(c[2]), "+f"(c[3])
        : "r"(a[0]), "r"(a[1]), "r"(a[2]), "r"(a[3]), "r"(b[0]), "r"(b[1]));
}

// ---------------------------------------------------------------------------
// Kernel 0-3: scaffolding (frozen since R5)
// ---------------------------------------------------------------------------
__global__ void reset_kernel() {
    int id = blockIdx.x * blockDim.x + threadIdx.x;
    if (id < MAXPAIR) g_pair_token[id] = -1;
    if (id < NE) { g_counts[id] = 0; g_cursor[id] = 0; }
}

__global__ void router_kernel(const float* __restrict__ x,
                              const float* __restrict__ gw,
                              float* __restrict__ logits_out,
                              int write_logits) {
    __shared__ float gwT[NE][HDIM];
    int tid = threadIdx.x;
    for (int idx = tid; idx < HDIM * NE; idx += 256) {
        int h = idx >> 3, e = idx & 7;
        gwT[e][h] = gw[idx];
    }
    __syncthreads();

    int warp = tid >> 5, lane = tid & 31;
    int t = blockIdx.x * 8 + warp;

    float acc[NE];
#pragma unroll
    for (int e = 0; e < NE; e++) acc[e] = 0.f;
    const float* xr = x + (size_t)t * HDIM;
    for (int i = lane; i < HDIM; i += 32) {
        float xv = xr[i];
#pragma unroll
        for (int e = 0; e < NE; e++) acc[e] += xv * gwT[e][i];
    }
#pragma unroll
    for (int e = 0; e < NE; e++)
        for (int off = 16; off; off >>= 1)
            acc[e] += __shfl_down_sync(0xffffffffu, acc[e], off);

    if (lane == 0) {
        if (write_logits) {
#pragma unroll
            for (int e = 0; e < NE; e++) logits_out[t * NE + e] = acc[e];
        }
        float l1 = -INFINITY, l2 = -INFINITY;
        int i1 = 0, i2 = 0;
#pragma unroll
        for (int e = 0; e < NE; e++) {
            float v = acc[e];
            if (v > l1)      { l2 = l1; i2 = i1; l1 = v; i1 = e; }
            else if (v > l2) { l2 = v; i2 = e; }
        }
        float b = expf(l2 - l1);
        float s = 1.f + b;
        g_tok_e[2 * t] = i1;  g_tok_e[2 * t + 1] = i2;
        g_tok_w[2 * t] = 1.f / s;
        g_tok_w[2 * t + 1] = b / s;
        atomicAdd(&g_counts[i1], 1);
        atomicAdd(&g_counts[i2], 1);
    }
}

__global__ void scan_kernel() {
    int s = 0;
    for (int e = 0; e < NE; e++) {
        g_seg[e] = s;
        s += ((g_counts[e] + BM - 1) / BM) * BM;
    }
    g_seg[NE] = s;
}

__global__ void assign_kernel() {
    int id = blockIdx.x * blockDim.x + threadIdx.x;
    if (id >= NT * TOPK) return;
    int e = g_tok_e[id];
    int pos = atomicAdd(&g_cursor[e], 1);
    int p = g_seg[e] + pos;
    g_pair_token[p] = id >> 1;
    g_tok_pair[id] = p;
}

// ---------------------------------------------------------------------------
// BIG GEMM: 128x256x32 tiles, 4-stage cp.async pipeline, 256 threads.
//   PHASE1 (GATHER=1): A = x via g_pair_token, B = w1[e], Out = g_hbuf (+relu)
//   PHASE2 (GATHER=0): A = g_hbuf,             B = w2[e], Out = g_ybuf
// ---------------------------------------------------------------------------
template <int GATHER, int RELU>
__global__ __launch_bounds__(256, 1)
void moe_mma_big(const float* __restrict__ Xarg,
                 const float* __restrict__ B, int K, int ldN) {
    extern __shared__ float smf[];

    const float* Abase = GATHER ? Xarg : g_hbuf;
    float* Out         = GATHER ? g_hbuf : g_ybuf;

    int m0 = blockIdx.y * BM;
    if (m0 >= g_seg[NE]) return;
    int n0 = blockIdx.x * B_BN;

    int e = 0;
#pragma unroll
    for (int i = 1; i < NE; i++) if (m0 >= g_seg[i]) e = i;
    const float* Bexp = B + (size_t)e * K * ldN;

    int tid = threadIdx.x;
    int warp = tid >> 5, lane = tid & 31;
    int warpM = warp >> 2, warpN = warp & 3;    // 2 x 4 warp grid

    // A: thread owns row tid>>1, half (tid&1)*16 floats (4 x cp16)
    int arow = tid >> 1, ahalf = (tid & 1) * 16;
    const float* aG;
    if (GATHER) {
        int tk = g_pair_token[m0 + arow];
        aG = ((tk >= 0) ? (Abase + (size_t)tk * K) : g_zrow) + ahalf;
    } else {
        aG = Abase + (size_t)(m0 + arow) * K + ahalf;
    }
    // B: thread owns k-row tid>>3, cols (tid&7)*32..+31 (8 x cp16)
    int bkr = tid >> 3, bcg = (tid & 7) * 32;
    const float* bG = Bexp + (size_t)bkr * ldN + n0 + bcg;

    uint32_t sbase = smem_u32(smf);
    uint32_t aS = sbase + (uint32_t)(arow * B_ASTR + ahalf) * 4u;
    uint32_t bS = sbase + (uint32_t)B_ABYTES + (uint32_t)(bkr * B_BSTR + bcg) * 4u;

    const int NC = K / B_KC;

    float c[4][8][4];
#pragma unroll
    for (int ti = 0; ti < 4; ti++)
#pragma unroll
        for (int tj = 0; tj < 8; tj++)
#pragma unroll
            for (int q = 0; q < 4; q++) c[ti][tj][q] = 0.f;

    int amBase = warpM * 64 + (lane >> 2);
    int bnBase = warpN * 64 + (lane >> 2);
    int kl = lane & 3;

    // ---- prologue: chunks 0,1,2
#pragma unroll
    for (int ch = 0; ch < 3; ch++) {
        uint32_t so = (uint32_t)(ch * B_STAGE_BYTES);
        size_t ko = (size_t)ch * B_KC;
#pragma unroll
        for (int j = 0; j < 4; j++) cp16(aS + so + j * 16, aG + ko + j * 4);
#pragma unroll
        for (int j = 0; j < 8; j++) cp16(bS + so + j * 16, bG + ko * ldN + j * 4);
        cp_commit();
    }

    for (int i = 0; i < NC; i++) {
        // drain so chunk i is complete (tail-aware)
        int rem = NC - 1 - i;               // committed beyond i
        if (rem >= 2) cp_wait2();
        else if (rem == 1) cp_wait1();
        else cp_wait0();
        __syncthreads();    // data visible to all; stage (i-1)&3 free for reuse

        if (i + 3 < NC) {
            uint32_t so = (uint32_t)(((i + 3) & 3) * B_STAGE_BYTES);
            size_t ko = (size_t)(i + 3) * B_KC;
#pragma unroll
            for (int j = 0; j < 4; j++) cp16(aS + so + j * 16, aG + ko + j * 4);
#pragma unroll
            for (int j = 0; j < 8; j++) cp16(bS + so + j * 16, bG + ko * ldN + j * 4);
            cp_commit();
        }

        const float* As = smf + (i & 3) * B_STAGE_FLOATS;
        const float* Bs = As + BM * B_ASTR;

#pragma unroll
        for (int s = 0; s < B_KC / 8; s++) {
            int k0 = s * 8 + kl;
            uint32_t a[4][4], b[8][2];
#pragma unroll
            for (int ti = 0; ti < 4; ti++) {
                int m = amBase + ti * 16;
                a[ti][0] = f2tf(As[m * B_ASTR + k0]);
                a[ti][1] = f2tf(As[(m + 8) * B_ASTR + k0]);
                a[ti][2] = f2tf(As[m * B_ASTR + k0 + 4]);
                a[ti][3] = f2tf(As[(m + 8) * B_ASTR + k0 + 4]);
            }
#pragma unroll
            for (int tj = 0; tj < 8; tj++) {
                int n = bnBase + tj * 8;
                b[tj][0] = f2tf(Bs[k0 * B_BSTR + n]);
                b[tj][1] = f2tf(Bs[(k0 + 4) * B_BSTR + n]);
            }
#pragma unroll
            for (int ti = 0; ti < 4; ti++)
#pragma unroll
                for (int tj = 0; tj < 8; tj++)
                    mma_tf32(c[ti][tj], a[ti], b[tj]);
        }
    }

    // ---- epilogue
    int cm = m0 + warpM * 64 + (lane >> 2);
    int cn = n0 + warpN * 64 + (lane & 3) * 2;
#pragma unroll
    for (int ti = 0; ti < 4; ti++) {
#pragma unroll
        for (int tj = 0; tj < 8; tj++) {
            float v0 = c[ti][tj][0], v1 = c[ti][tj][1];
            float v2 = c[ti][tj][2], v3 = c[ti][tj][3];
            if (RELU) {
                v0 = fmaxf(v0, 0.f); v1 = fmaxf(v1, 0.f);
                v2 = fmaxf(v2, 0.f); v3 = fmaxf(v3, 0.f);
            }
            size_t r0 = (size_t)(cm + ti * 16) * ldN + cn + tj * 8;
            size_t r1 = (size_t)(cm + ti * 16 + 8) * ldN + cn + tj * 8;
            *(float2*)(Out + r0) = make_float2(v0, v1);
            *(float2*)(Out + r1) = make_float2(v2, v3);
        }
    }
}

// ---------------------------------------------------------------------------
// SMALL GEMM: exact R9 kernel (fallback if smem opt-in fails), BSTR fixed 136
// ---------------------------------------------------------------------------
template <int GATHER, int RELU>
__global__ __launch_bounds__(128)
void moe_mma_small(const float* __restrict__ Xarg,
                   const float* __restrict__ B, int K, int ldN) {
    __shared__ float smf[2 * S_STAGE_FLOATS];

    const float* Abase = GATHER ? Xarg : g_hbuf;
    float* Out         = GATHER ? g_hbuf : g_ybuf;

    int m0 = blockIdx.y * BM;
    if (m0 >= g_seg[NE]) return;
    int n0 = blockIdx.x * S_BN;

    int e = 0;
#pragma unroll
    for (int i = 1; i < NE; i++) if (m0 >= g_seg[i]) e = i;
    const float* Bexp = B + (size_t)e * K * ldN;

    int tid = threadIdx.x;
    int warp = tid >> 5, lane = tid & 31;

    const float* aG;
    if (GATHER) {
        int tk = g_pair_token[m0 + tid];
        aG = (tk >= 0) ? (Abase + (size_t)tk * K) : g_zrow;
    } else {
        aG = Abase + (size_t)(m0 + tid) * K;
    }
    const float* bG = Bexp + (size_t)(tid >> 3) * ldN + n0 + (tid & 7) * 16;

    uint32_t sbase = smem_u32(smf);
    uint32_t aS = sbase + (uint32_t)(tid * S_ASTR) * 4u;
    uint32_t bS = sbase + (uint32_t)S_ABYTES +
                  (uint32_t)((tid >> 3) * S_BSTR) * 4u + (uint32_t)((tid & 7) * 64);

    const int NC = K / S_KC;

    float c[4][8][4];
#pragma unroll
    for (int ti = 0; ti < 4; ti++)
#pragma unroll
        for (int tj = 0; tj < 8; tj++)
#pragma unroll
            for (int q = 0; q < 4; q++) c[ti][tj][q] = 0.f;

    int amBase = (warp >> 1) * 64 + (lane >> 2);
    int bnBase = (warp & 1) * 64 + (lane >> 2);
    int kl = lane & 3;

#pragma unroll
    for (int j = 0; j < 4; j++) cp16(aS + j * 16, aG + j * 4);
#pragma unroll
    for (int j = 0; j < 4; j++) cp16(bS + j * 16, bG + j * 4);
    cp_commit();

    for (int i = 0; i < NC; i++) {
        if (i + 1 < NC) {
            uint32_t so = (uint32_t)(((i + 1) & 1) * S_STAGE_BYTES);
            size_t ko = (size_t)(i + 1) * S_KC;
#pragma unroll
            for (int j = 0; j < 4; j++) cp16(aS + so + j * 16, aG + ko + j * 4);
#pragma unroll
            for (int j = 0; j < 4; j++) cp16(bS + so + j * 16, bG + ko * ldN + j * 4);
            cp_commit();
            cp_wait1();
        } else {
            cp_wait0();
        }
        __syncthreads();

        const float* As = smf + (i & 1) * S_STAGE_FLOATS;
        const float* Bs = As + BM * S_ASTR;

#pragma unroll
        for (int s = 0; s < S_KC / 8; s++) {
            int k0 = s * 8 + kl;
            uint32_t a[4][4], b[8][2];
#pragma unroll
            for (int ti = 0; ti < 4; ti++) {
                int m = amBase + ti * 16;
                a[ti][0] = f2tf(As[m * S_ASTR + k0]);
                a[ti][1] = f2tf(As[(m + 8) * S_ASTR + k0]);
                a[ti][2] = f2tf(As[m * S_ASTR + k0 + 4]);
                a[ti][3] = f2tf(As[(m + 8) * S_ASTR + k0 + 4]);
            }
#pragma unroll
            for (int tj = 0; tj < 8; tj++) {
                int n = bnBase + tj * 8;
                b[tj][0] = f2tf(Bs[k0 * S_BSTR + n]);
                b[tj][1] = f2tf(Bs[(k0 + 4) * S_BSTR + n]);
            }
#pragma unroll
            for (int ti = 0; ti < 4; ti++)
#pragma unroll
                for (int tj = 0; tj < 8; tj++)
                    mma_tf32(c[ti][tj], a[ti], b[tj]);
        }
        __syncthreads();
    }

    int cm = m0 + (warp >> 1) * 64 + (lane >> 2);
    int cn = n0 + (warp & 1) * 64 + (lane & 3) * 2;
#pragma unroll
    for (int ti = 0; ti < 4; ti++) {
#pragma unroll
        for (int tj = 0; tj < 8; tj++) {
            float v0 = c[ti][tj][0], v1 = c[ti][tj][1];
            float v2 = c[ti][tj][2], v3 = c[ti][tj][3];
            if (RELU) {
                v0 = fmaxf(v0, 0.f); v1 = fmaxf(v1, 0.f);
                v2 = fmaxf(v2, 0.f); v3 = fmaxf(v3, 0.f);
            }
            size_t r0 = (size_t)(cm + ti * 16) * ldN + cn + tj * 8;
            size_t r1 = (size_t)(cm + ti * 16 + 8) * ldN + cn + tj * 8;
            *(float2*)(Out + r0) = make_float2(v0, v1);
            *(float2*)(Out + r1) = make_float2(v2, v3);
        }
    }
}

// ---------------------------------------------------------------------------
// Kernel: combine
// ---------------------------------------------------------------------------
__global__ void combine_kernel(float* __restrict__ out) {
    int t = blockIdx.x;
    int j = threadIdx.x * 4;
    int p0 = g_tok_pair[2 * t], p1 = g_tok_pair[2 * t + 1];
    float w0 = g_tok_w[2 * t], w1 = g_tok_w[2 * t + 1];
    float4 y0 = *(const float4*)(g_ybuf + (size_t)p0 * HDIM + j);
    float4 y1 = *(const float4*)(g_ybuf + (size_t)p1 * HDIM + j);
    float4 r;
    r.x = w0 * y0.x + w1 * y1.x;
    r.y = w0 * y0.y + w1 * y1.y;
    r.z = w0 * y0.z + w1 * y1.z;
    r.w = w0 * y0.w + w1 * y1.w;
    *(float4*)(out + (size_t)t * HDIM + j) = r;
}

// ---------------------------------------------------------------------------
// Launch — only harness pointers cross host/device; big path gated on the
// verified success of the smem opt-in, else proven R9 fallback.
// ---------------------------------------------------------------------------
extern "C" void kernel_launch(void* const* d_in, const int* in_sizes, int n_in,
                              void* d_out, int out_size) {
    const float* x  = (const float*)d_in[0];
    const float* gw = (const float*)d_in[1];
    const float* w1 = (const float*)d_in[2];
    const float* w2 = (const float*)d_in[3];
    float* out = (float*)d_out;

    int write_logits = (out_size >= NT * HDIM + NT * NE) ? 1 : 0;

    cudaError_t e1 = cudaFuncSetAttribute(
        (const void*)moe_mma_big<1, 1>,
        cudaFuncAttributeMaxDynamicSharedMemorySize, SMEM_BIG);
    cudaError_t e2 = cudaFuncSetAttribute(
        (const void*)moe_mma_big<0, 0>,
        cudaFuncAttributeMaxDynamicSharedMemorySize, SMEM_BIG);
    bool big = (e1 == cudaSuccess && e2 == cudaSuccess);

    reset_kernel<<<(MAXPAIR + 255) / 256, 256>>>();
    router_kernel<<<NT / 8, 256>>>(x, gw, out + (size_t)NT * HDIM, write_logits);
    scan_kernel<<<1, 1>>>();
    assign_kernel<<<(NT * TOPK + 255) / 256, 256>>>();

    if (big) {
        moe_mma_big<1, 1><<<dim3(FDIM / B_BN, MTILES), 256, SMEM_BIG>>>(
            x, w1, HDIM, FDIM);
        moe_mma_big<0, 0><<<dim3(HDIM / B_BN, MTILES), 256, SMEM_BIG>>>(
            x, w2, FDIM, HDIM);
    } else {
        moe_mma_small<1, 1><<<dim3(FDIM / S_BN, MTILES), 128>>>(x, w1, HDIM, FDIM);
        moe_mma_small<0, 0><<<dim3(HDIM / S_BN, MTILES), 128>>>(x, w2, FDIM, HDIM);
    }
    combine_kernel<<<NT, 256>>>(out);
}

// round 11
// speedup vs baseline: 1.0281x; 1.0281x over previous
#include <cuda_runtime.h>
#include <math.h>
#include <stdint.h>

// Shapes (fixed by reference)
#define NT    8192
#define HDIM  1024
#define FDIM  4096
#define NE    8
#define TOPK  2

// GEMM tiling (R9-proven): 128x128x16, 2 stages, 128 threads
#define BM 128
#define BN 128
#define KC 16
#define ASTR 20          // bank (20m+k)%32: all 32 distinct — conflict-free
#define BSTR 136         // ==8 mod 32: bank 8k+n covers all 32 — conflict-free
#define STAGE_FLOATS (BM * ASTR + KC * BSTR)   // 2560+2176 = 4736
#define ABYTES (BM * ASTR * 4)
#define STAGE_BYTES (STAGE_FLOATS * 4)         // 18944; x2 = 37888 < 48K

#define MAXPAIR (NT * TOPK + NE * BM)   // 17408
#define MTILES  (MAXPAIR / BM)          // 136

// ---------------------------------------------------------------------------
// Scratch (device symbols: referenced ONLY from device code — host-side
// symbol args were the R7/R8 silent-zeros bug via GB300 ATS)
// ---------------------------------------------------------------------------
__device__ int   g_counts[NE];
__device__ int   g_cursor[NE];
__device__ int   g_seg[NE + 1];
__device__ int   g_pair_token[MAXPAIR];
__device__ int   g_tok_e[NT * TOPK];
__device__ float g_tok_w[NT * TOPK];
__device__ int   g_tok_pair[NT * TOPK];
__device__ float g_zrow[HDIM];                       // never written: zeros
__device__ float g_xr [(size_t)NT * HDIM];           // tf32-rounded x
__device__ float g_w1r[(size_t)NE * HDIM * FDIM];    // tf32-rounded w1
__device__ float g_w2r[(size_t)NE * FDIM * HDIM];    // tf32-rounded w2
__device__ float g_hbuf[(size_t)MAXPAIR * FDIM];     // relu(x@w1), tf32-rounded
__device__ float g_ybuf[(size_t)MAXPAIR * HDIM];

// ---------------------------------------------------------------------------
// PTX helpers (non-arch-specific: legal on compute_103)
// ---------------------------------------------------------------------------
__device__ __forceinline__ uint32_t smem_u32(const void* p) {
    uint32_t a;
    asm("{ .reg .u64 t; cvta.to.shared.u64 t, %1; cvt.u32.u64 %0, t; }"
        : "=r"(a) : "l"(p));
    return a;
}
__device__ __forceinline__ float to_tf32(float x) {
    uint32_t u;
    asm("cvt.rna.tf32.f32 %0, %1;" : "=r"(u) : "f"(x));
    return __uint_as_float(u);
}
__device__ __forceinline__ void cp16(uint32_t s, const float* g) {
    asm volatile("cp.async.cg.shared.global [%0], [%1], 16;"
                 :: "r"(s), "l"(g) : "memory");
}
__device__ __forceinline__ void cp_commit() {
    asm volatile("cp.async.commit_group;" ::: "memory");
}
__device__ __forceinline__ void cp_wait1() {
    asm volatile("cp.async.wait_group 1;" ::: "memory");
}
__device__ __forceinline__ void cp_wait0() {
    asm volatile("cp.async.wait_group 0;" ::: "memory");
}
__device__ __forceinline__ void mma_tf32(float* c, const uint32_t* a,
                                         const uint32_t* b) {
    asm volatile(
        "mma.sync.aligned.m16n8k8.row.col.f32.tf32.tf32.f32 "
        "{%0,%1,%2,%3}, {%4,%5,%6,%7}, {%8,%9}, {%0,%1,%2,%3};"
        : "+f"(c[0]), "+f"(c[1]), "+f"(c[2]), "+f"(c[3])
        : "r"(a[0]), "r"(a[1]), "r"(a[2]), "r"(a[3]), "r"(b[0]), "r"(b[1]));
}

// ---------------------------------------------------------------------------
// Kernel 0-3: scaffolding (frozen since R5)
// ---------------------------------------------------------------------------
__global__ void reset_kernel() {
    int id = blockIdx.x * blockDim.x + threadIdx.x;
    if (id < MAXPAIR) g_pair_token[id] = -1;
    if (id < NE) { g_counts[id] = 0; g_cursor[id] = 0; }
}

__global__ void router_kernel(const float* __restrict__ x,
                              const float* __restrict__ gw,
                              float* __restrict__ logits_out,
                              int write_logits) {
    __shared__ float gwT[NE][HDIM];
    int tid = threadIdx.x;
    for (int idx = tid; idx < HDIM * NE; idx += 256) {
        int h = idx >> 3, e = idx & 7;
        gwT[e][h] = gw[idx];
    }
    __syncthreads();

    int warp = tid >> 5, lane = tid & 31;
    int t = blockIdx.x * 8 + warp;

    float acc[NE];
#pragma unroll
    for (int e = 0; e < NE; e++) acc[e] = 0.f;
    const float* xr = x + (size_t)t * HDIM;
    for (int i = lane; i < HDIM; i += 32) {
        float xv = xr[i];
#pragma unroll
        for (int e = 0; e < NE; e++) acc[e] += xv * gwT[e][i];
    }
#pragma unroll
    for (int e = 0; e < NE; e++)
        for (int off = 16; off; off >>= 1)
            acc[e] += __shfl_down_sync(0xffffffffu, acc[e], off);

    if (lane == 0) {
        if (write_logits) {
#pragma unroll
            for (int e = 0; e < NE; e++) logits_out[t * NE + e] = acc[e];
        }
        float l1 = -INFINITY, l2 = -INFINITY;
        int i1 = 0, i2 = 0;
#pragma unroll
        for (int e = 0; e < NE; e++) {
            float v = acc[e];
            if (v > l1)      { l2 = l1; i2 = i1; l1 = v; i1 = e; }
            else if (v > l2) { l2 = v; i2 = e; }
        }
        float b = expf(l2 - l1);
        float s = 1.f + b;
        g_tok_e[2 * t] = i1;  g_tok_e[2 * t + 1] = i2;
        g_tok_w[2 * t] = 1.f / s;
        g_tok_w[2 * t + 1] = b / s;
        atomicAdd(&g_counts[i1], 1);
        atomicAdd(&g_counts[i2], 1);
    }
}

__global__ void scan_kernel() {
    int s = 0;
    for (int e = 0; e < NE; e++) {
        g_seg[e] = s;
        s += ((g_counts[e] + BM - 1) / BM) * BM;
    }
    g_seg[NE] = s;
}

__global__ void assign_kernel() {
    int id = blockIdx.x * blockDim.x + threadIdx.x;
    if (id >= NT * TOPK) return;
    int e = g_tok_e[id];
    int pos = atomicAdd(&g_cursor[e], 1);
    int p = g_seg[e] + pos;
    g_pair_token[p] = id >> 1;
    g_tok_pair[id] = p;
}

// ---------------------------------------------------------------------------
// Kernel 4: tf32 pre-rounding pass (once per launch; dst chosen device-side)
//   DST: 0 -> g_xr, 1 -> g_w1r, 2 -> g_w2r
//   Values identical to rounding at fragment-load time -> bit-identical output
// ---------------------------------------------------------------------------
template <int DST>
__global__ void round_kernel(const float* __restrict__ src, size_t n4) {
    float* dst = (DST == 0) ? g_xr : (DST == 1) ? g_w1r : g_w2r;
    for (size_t i = blockIdx.x * blockDim.x + threadIdx.x; i < n4;
         i += (size_t)gridDim.x * blockDim.x) {
        float4 v = ((const float4*)src)[i];
        v.x = to_tf32(v.x); v.y = to_tf32(v.y);
        v.z = to_tf32(v.z); v.w = to_tf32(v.w);
        ((float4*)dst)[i] = v;
    }
}

// ---------------------------------------------------------------------------
// Kernel 5: tf32 mma.sync GEMM — NO conversions in the hot loop.
//   PHASE1 (GATHER=1): A = g_xr via g_pair_token, B = g_w1r[e] -> g_hbuf (+relu+round)
//   PHASE2 (GATHER=0): A = g_hbuf (pre-rounded),  B = g_w2r[e] -> g_ybuf
// ---------------------------------------------------------------------------
template <int GATHER, int RELU>
__global__ __launch_bounds__(128)
void moe_mma_kernel(int K, int ldN) {
    __shared__ float smf[2 * STAGE_FLOATS];

    const float* Abase = GATHER ? g_xr : g_hbuf;
    const float* Bbase = GATHER ? g_w1r : g_w2r;
    float* Out         = GATHER ? g_hbuf : g_ybuf;

    int m0 = blockIdx.y * BM;
    if (m0 >= g_seg[NE]) return;
    int n0 = blockIdx.x * BN;

    int e = 0;
#pragma unroll
    for (int i = 1; i < NE; i++) if (m0 >= g_seg[i]) e = i;
    const float* Bexp = Bbase + (size_t)e * K * ldN;

    int tid = threadIdx.x;
    int warp = tid >> 5, lane = tid & 31;

    // A: thread t owns row t, k 0..15 (4 x cp16)
    // B: thread t owns k-row t>>3, cols (t&7)*16..+15 (4 x cp16)
    const float* aG;
    if (GATHER) {
        int tk = g_pair_token[m0 + tid];
        aG = (tk >= 0) ? (Abase + (size_t)tk * K) : g_zrow;
    } else {
        aG = Abase + (size_t)(m0 + tid) * K;
    }
    const float* bG = Bexp + (size_t)(tid >> 3) * ldN + n0 + (tid & 7) * 16;

    uint32_t sbase = smem_u32(smf);
    uint32_t aS = sbase + (uint32_t)(tid * ASTR) * 4u;
    uint32_t bS = sbase + (uint32_t)ABYTES +
                  (uint32_t)((tid >> 3) * BSTR) * 4u + (uint32_t)((tid & 7) * 64);

    const int NC = K / KC;

    float c[4][8][4];
#pragma unroll
    for (int ti = 0; ti < 4; ti++)
#pragma unroll
        for (int tj = 0; tj < 8; tj++)
#pragma unroll
            for (int q = 0; q < 4; q++) c[ti][tj][q] = 0.f;

    int amBase = (warp >> 1) * 64 + (lane >> 2);
    int bnBase = (warp & 1) * 64 + (lane >> 2);
    int kl = lane & 3;

    // ---- prologue: chunk 0
#pragma unroll
    for (int j = 0; j < 4; j++) cp16(aS + j * 16, aG + j * 4);
#pragma unroll
    for (int j = 0; j < 4; j++) cp16(bS + j * 16, bG + j * 4);
    cp_commit();

    for (int i = 0; i < NC; i++) {
        if (i + 1 < NC) {
            uint32_t so = (uint32_t)(((i + 1) & 1) * STAGE_BYTES);
            size_t ko = (size_t)(i + 1) * KC;
#pragma unroll
            for (int j = 0; j < 4; j++) cp16(aS + so + j * 16, aG + ko + j * 4);
#pragma unroll
            for (int j = 0; j < 4; j++) cp16(bS + so + j * 16, bG + ko * ldN + j * 4);
            cp_commit();
            cp_wait1();
        } else {
            cp_wait0();
        }
        __syncthreads();

        // raw bit-pattern loads: data already tf32-rounded, no CVT needed
        const uint32_t* As = (const uint32_t*)(smf + (i & 1) * STAGE_FLOATS);
        const uint32_t* Bs = As + BM * ASTR;

#pragma unroll
        for (int s = 0; s < KC / 8; s++) {
            int k0 = s * 8 + kl;
            uint32_t a[4][4], b[8][2];
#pragma unroll
            for (int ti = 0; ti < 4; ti++) {
                int m = amBase + ti * 16;
                a[ti][0] = As[m * ASTR + k0];
                a[ti][1] = As[(m + 8) * ASTR + k0];
                a[ti][2] = As[m * ASTR + k0 + 4];
                a[ti][3] = As[(m + 8) * ASTR + k0 + 4];
            }
#pragma unroll
            for (int tj = 0; tj < 8; tj++) {
                int n = bnBase + tj * 8;
                b[tj][0] = Bs[k0 * BSTR + n];
                b[tj][1] = Bs[(k0 + 4) * BSTR + n];
            }
#pragma unroll
            for (int ti = 0; ti < 4; ti++)
#pragma unroll
                for (int tj = 0; tj < 8; tj++)
                    mma_tf32(c[ti][tj], a[ti], b[tj]);
        }
        __syncthreads();
    }

    // ---- epilogue: phase1 also rounds to tf32 so GEMM2 needs no loop CVTs
    int cm = m0 + (warp >> 1) * 64 + (lane >> 2);
    int cn = n0 + (warp & 1) * 64 + (lane & 3) * 2;
#pragma unroll
    for (int ti = 0; ti < 4; ti++) {
#pragma unroll
        for (int tj = 0; tj < 8; tj++) {
            float v0 = c[ti][tj][0], v1 = c[ti][tj][1];
            float v2 = c[ti][tj][2], v3 = c[ti][tj][3];
            if (RELU) {
                v0 = to_tf32(fmaxf(v0, 0.f)); v1 = to_tf32(fmaxf(v1, 0.f));
                v2 = to_tf32(fmaxf(v2, 0.f)); v3 = to_tf32(fmaxf(v3, 0.f));
            }
            size_t r0 = (size_t)(cm + ti * 16) * ldN + cn + tj * 8;
            size_t r1 = (size_t)(cm + ti * 16 + 8) * ldN + cn + tj * 8;
            *(float2*)(Out + r0) = make_float2(v0, v1);
            *(float2*)(Out + r1) = make_float2(v2, v3);
        }
    }
}

// ---------------------------------------------------------------------------
// Kernel 6: combine — out[t] = w0 * ybuf[p0] + w1 * ybuf[p1]
// ---------------------------------------------------------------------------
__global__ void combine_kernel(float* __restrict__ out) {
    int t = blockIdx.x;
    int j = threadIdx.x * 4;
    int p0 = g_tok_pair[2 * t], p1 = g_tok_pair[2 * t + 1];
    float w0 = g_tok_w[2 * t], w1 = g_tok_w[2 * t + 1];
    float4 y0 = *(const float4*)(g_ybuf + (size_t)p0 * HDIM + j);
    float4 y1 = *(const float4*)(g_ybuf + (size_t)p1 * HDIM + j);
    float4 r;
    r.x = w0 * y0.x + w1 * y1.x;
    r.y = w0 * y0.y + w1 * y1.y;
    r.z = w0 * y0.z + w1 * y1.z;
    r.w = w0 * y0.w + w1 * y1.w;
    *(float4*)(out + (size_t)t * HDIM + j) = r;
}

// ---------------------------------------------------------------------------
// Launch — only harness pointers cross the host/device boundary
// ---------------------------------------------------------------------------
extern "C" void kernel_launch(void* const* d_in, const int* in_sizes, int n_in,
                              void* d_out, int out_size) {
    const float* x  = (const float*)d_in[0];
    const float* gw = (const float*)d_in[1];
    const float* w1 = (const float*)d_in[2];
    const float* w2 = (const float*)d_in[3];
    float* out = (float*)d_out;

    int write_logits = (out_size >= NT * HDIM + NT * NE) ? 1 : 0;

    reset_kernel<<<(MAXPAIR + 255) / 256, 256>>>();
    router_kernel<<<NT / 8, 256>>>(x, gw, out + (size_t)NT * HDIM, write_logits);
    scan_kernel<<<1, 1>>>();
    assign_kernel<<<(NT * TOPK + 255) / 256, 256>>>();

    // tf32 pre-rounding (values identical to in-loop cvt -> bit-identical out)
    round_kernel<0><<<592, 256>>>(x,  (size_t)NT * HDIM / 4);
    round_kernel<1><<<1184, 256>>>(w1, (size_t)NE * HDIM * FDIM / 4);
    round_kernel<2><<<1184, 256>>>(w2, (size_t)NE * FDIM * HDIM / 4);

    // GEMM1: g_hbuf[p,:F] = round(relu(xr[tok(p),:H] @ w1r[e]))  (K=H, ldN=F)
    moe_mma_kernel<1, 1><<<dim3(FDIM / BN, MTILES), 128>>>(HDIM, FDIM);
    // GEMM2: g_ybuf[p,:H] = g_hbuf[p,:F] @ w2r[e]                (K=F, ldN=H)
    moe_mma_kernel<0, 0><<<dim3(HDIM / BN, MTILES), 128>>>(FDIM, HDIM);
    combine_kernel<<<NT, 256>>>(out);
}

// round 12
// speedup vs baseline: 1.8083x; 1.7590x over previous
#include <cuda_runtime.h>
#include <cuda_fp16.h>
#include <math.h>
#include <stdint.h>

// Shapes (fixed by reference)
#define NT    8192
#define HDIM  1024
#define FDIM  4096
#define NE    8
#define TOPK  2

// GEMM tiling: 128x128 CTA, 4 warps (64x64), KC=32 half, 2 stages, fp16 MMA
#define BM 128
#define BN 128
#define KC 32                    // halfs per chunk = 16 u32 per row
#define RSTR 20                  // u32 row stride: bank (20g+r)%32 all-distinct
#define TILE_U32 (BM * RSTR)     // 2560 u32 per tile (A or B)
#define ABYTES (TILE_U32 * 4)    // 10240
#define STAGE_U32 (2 * TILE_U32) // 5120
#define STAGE_BYTES (STAGE_U32 * 4)  // 20480; x2 stages = 40960 < 48K

#define MAXPAIR (NT * TOPK + NE * BM)   // 17408
#define MTILES  (MAXPAIR / BM)          // 136

// ---------------------------------------------------------------------------
// Scratch (device symbols: referenced ONLY from device code — host-side
// symbol args were the R7/R8 silent-zeros bug via GB300 ATS)
// ---------------------------------------------------------------------------
__device__ int    g_counts[NE];
__device__ int    g_cursor[NE];
__device__ int    g_seg[NE + 1];
__device__ int    g_pair_token[MAXPAIR];
__device__ int    g_tok_e[NT * TOPK];
__device__ float  g_tok_w[NT * TOPK];
__device__ int    g_tok_pair[NT * TOPK];
__device__ __half g_zrow_h[HDIM];                       // never written: zeros
__device__ __half g_xh [(size_t)NT * HDIM];             // fp16 x
__device__ __half g_w1h[(size_t)NE * FDIM * HDIM];      // w1 as [E][F][H] fp16
__device__ __half g_w2h[(size_t)NE * HDIM * FDIM];      // w2 as [E][H][F] fp16
__device__ __half g_hbuf_h[(size_t)MAXPAIR * FDIM];     // relu(x@w1) fp16
__device__ float  g_ybuf[(size_t)MAXPAIR * HDIM];       // fp32 expert outputs

// ---------------------------------------------------------------------------
// PTX helpers (non-arch-specific: legal on compute_103)
// ---------------------------------------------------------------------------
__device__ __forceinline__ uint32_t smem_u32(const void* p) {
    uint32_t a;
    asm("{ .reg .u64 t; cvta.to.shared.u64 t, %1; cvt.u32.u64 %0, t; }"
        : "=r"(a) : "l"(p));
    return a;
}
__device__ __forceinline__ void cp16(uint32_t s, const void* g) {
    asm volatile("cp.async.cg.shared.global [%0], [%1], 16;"
                 :: "r"(s), "l"(g) : "memory");
}
__device__ __forceinline__ void cp_commit() {
    asm volatile("cp.async.commit_group;" ::: "memory");
}
__device__ __forceinline__ void cp_wait1() {
    asm volatile("cp.async.wait_group 1;" ::: "memory");
}
__device__ __forceinline__ void cp_wait0() {
    asm volatile("cp.async.wait_group 0;" ::: "memory");
}
// fp16 MMA, fp32 accumulate: m16n8k16 (sm_80+, not arch-specific)
__device__ __forceinline__ void mma_f16(float* c, const uint32_t* a,
                                        const uint32_t* b) {
    asm volatile(
        "mma.sync.aligned.m16n8k16.row.col.f32.f16.f16.f32 "
        "{%0,%1,%2,%3}, {%4,%5,%6,%7}, {%8,%9}, {%0,%1,%2,%3};"
        : "+f"(c[0]), "+f"(c[1]), "+f"(c[2]), "+f"(c[3])
        : "r"(a[0]), "r"(a[1]), "r"(a[2]), "r"(a[3]), "r"(b[0]), "r"(b[1]));
}

// ---------------------------------------------------------------------------
// Kernel 0-3: scaffolding (frozen since R5)
// ---------------------------------------------------------------------------
__global__ void reset_kernel() {
    int id = blockIdx.x * blockDim.x + threadIdx.x;
    if (id < MAXPAIR) g_pair_token[id] = -1;
    if (id < NE) { g_counts[id] = 0; g_cursor[id] = 0; }
}

__global__ void router_kernel(const float* __restrict__ x,
                              const float* __restrict__ gw,
                              float* __restrict__ logits_out,
                              int write_logits) {
    __shared__ float gwT[NE][HDIM];
    int tid = threadIdx.x;
    for (int idx = tid; idx < HDIM * NE; idx += 256) {
        int h = idx >> 3, e = idx & 7;
        gwT[e][h] = gw[idx];
    }
    __syncthreads();

    int warp = tid >> 5, lane = tid & 31;
    int t = blockIdx.x * 8 + warp;

    float acc[NE];
#pragma unroll
    for (int e = 0; e < NE; e++) acc[e] = 0.f;
    const float* xr = x + (size_t)t * HDIM;
    for (int i = lane; i < HDIM; i += 32) {
        float xv = xr[i];
#pragma unroll
        for (int e = 0; e < NE; e++) acc[e] += xv * gwT[e][i];
    }
#pragma unroll
    for (int e = 0; e < NE; e++)
        for (int off = 16; off; off >>= 1)
            acc[e] += __shfl_down_sync(0xffffffffu, acc[e], off);

    if (lane == 0) {
        if (write_logits) {
#pragma unroll
            for (int e = 0; e < NE; e++) logits_out[t * NE + e] = acc[e];
        }
        float l1 = -INFINITY, l2 = -INFINITY;
        int i1 = 0, i2 = 0;
#pragma unroll
        for (int e = 0; e < NE; e++) {
            float v = acc[e];
            if (v > l1)      { l2 = l1; i2 = i1; l1 = v; i1 = e; }
            else if (v > l2) { l2 = v; i2 = e; }
        }
        float b = expf(l2 - l1);
        float s = 1.f + b;
        g_tok_e[2 * t] = i1;  g_tok_e[2 * t + 1] = i2;
        g_tok_w[2 * t] = 1.f / s;
        g_tok_w[2 * t + 1] = b / s;
        atomicAdd(&g_counts[i1], 1);
        atomicAdd(&g_counts[i2], 1);
    }
}

__global__ void scan_kernel() {
    int s = 0;
    for (int e = 0; e < NE; e++) {
        g_seg[e] = s;
        s += ((g_counts[e] + BM - 1) / BM) * BM;
    }
    g_seg[NE] = s;
}

__global__ void assign_kernel() {
    int id = blockIdx.x * blockDim.x + threadIdx.x;
    if (id >= NT * TOPK) return;
    int e = g_tok_e[id];
    int pos = atomicAdd(&g_cursor[e], 1);
    int p = g_seg[e] + pos;
    g_pair_token[p] = id >> 1;
    g_tok_pair[id] = p;
}

// ---------------------------------------------------------------------------
// Kernel 4: x -> fp16 (elementwise)
// ---------------------------------------------------------------------------
__global__ void convert_x_kernel(const float* __restrict__ x) {
    size_t n = (size_t)NT * HDIM;
    for (size_t i = blockIdx.x * blockDim.x + threadIdx.x; i < n;
         i += (size_t)gridDim.x * blockDim.x) {
        g_xh[i] = __float2half_rn(x[i]);
    }
}

// ---------------------------------------------------------------------------
// Kernel 5: transpose + convert weights: src [E][R][C] f32 -> dst [E][C][R] fp16
//   DST: 1 -> g_w1h (R=HDIM,C=FDIM), 2 -> g_w2h (R=FDIM,C=HDIM)
// ---------------------------------------------------------------------------
template <int DST>
__global__ void transpose_h_kernel(const float* __restrict__ src, int R, int C) {
    __shared__ float tile[32][33];
    __half* dstB = (DST == 1) ? g_w1h : g_w2h;
    int e = blockIdx.z;
    int c0 = blockIdx.x * 32, r0 = blockIdx.y * 32;
    const float* s = src + (size_t)e * R * C;
    __half* d = dstB + (size_t)e * R * C;
    int tx = threadIdx.x, ty = threadIdx.y;   // 32 x 8
#pragma unroll
    for (int i = 0; i < 32; i += 8)
        tile[ty + i][tx] = s[(size_t)(r0 + ty + i) * C + c0 + tx];
    __syncthreads();
#pragma unroll
    for (int i = 0; i < 32; i += 8)
        d[(size_t)(c0 + ty + i) * R + r0 + tx] = __float2half_rn(tile[tx][ty + i]);
}

// ---------------------------------------------------------------------------
// Kernel 6: fp16 mma.sync GEMM.  D[m,n] = A[m,:K] @ B[n,:K]^T
//   A: [rows][K] half (gathered from g_xh in phase 1, g_hbuf_h in phase 2)
//   B: [E][N][K] half (pre-transposed) — SAME smem structure as A.
//   PHASE1 (GATHER=1): Out = g_hbuf_h (fp16, +relu). PHASE2: Out = g_ybuf (f32).
// ---------------------------------------------------------------------------
template <int GATHER>
__global__ __launch_bounds__(128)
void moe_mma_f16_kernel(int K, int ldOut) {
    __shared__ uint32_t sm[2 * STAGE_U32];

    const __half* Abase = GATHER ? g_xh : g_hbuf_h;
    const __half* Bbase = GATHER ? g_w1h : g_w2h;

    int m0 = blockIdx.y * BM;
    if (m0 >= g_seg[NE]) return;
    int n0 = blockIdx.x * BN;

    int e = 0;
#pragma unroll
    for (int i = 1; i < NE; i++) if (m0 >= g_seg[i]) e = i;
    const __half* Bexp = Bbase + (size_t)e * (size_t)ldOut * K;  // [N][K], N=ldOut

    int tid = threadIdx.x;
    int warp = tid >> 5, lane = tid & 31;

    // load mapping: thread t owns A row t and B row (n0+t), each 32 half = 4 cp16
    const __half* aG;
    if (GATHER) {
        int tk = g_pair_token[m0 + tid];
        aG = (tk >= 0) ? (Abase + (size_t)tk * K) : g_zrow_h;
    } else {
        aG = Abase + (size_t)(m0 + tid) * K;
    }
    const __half* bG = Bexp + (size_t)(n0 + tid) * K;

    uint32_t sbase = smem_u32(sm);
    uint32_t aS = sbase + (uint32_t)(tid * RSTR) * 4u;
    uint32_t bS = sbase + (uint32_t)ABYTES + (uint32_t)(tid * RSTR) * 4u;

    const int NC = K / KC;

    float c[4][8][4];
#pragma unroll
    for (int ti = 0; ti < 4; ti++)
#pragma unroll
        for (int tj = 0; tj < 8; tj++)
#pragma unroll
            for (int q = 0; q < 4; q++) c[ti][tj][q] = 0.f;

    int amBase = (warp >> 1) * 64 + (lane >> 2);
    int bnBase = (warp & 1) * 64 + (lane >> 2);
    int kl = lane & 3;

    // ---- prologue: chunk 0
#pragma unroll
    for (int j = 0; j < 4; j++) cp16(aS + j * 16, aG + j * 8);
#pragma unroll
    for (int j = 0; j < 4; j++) cp16(bS + j * 16, bG + j * 8);
    cp_commit();

    for (int i = 0; i < NC; i++) {
        if (i + 1 < NC) {
            uint32_t so = (uint32_t)(((i + 1) & 1) * STAGE_BYTES);
            size_t ko = (size_t)(i + 1) * KC;
#pragma unroll
            for (int j = 0; j < 4; j++) cp16(aS + so + j * 16, aG + ko + j * 8);
#pragma unroll
            for (int j = 0; j < 4; j++) cp16(bS + so + j * 16, bG + ko + j * 8);
            cp_commit();
            cp_wait1();
        } else {
            cp_wait0();
        }
        __syncthreads();

        const uint32_t* As = sm + (i & 1) * STAGE_U32;
        const uint32_t* Bs = As + TILE_U32;

        // 2 k16-steps per chunk (KC=32 half)
#pragma unroll
        for (int s = 0; s < 2; s++) {
            int kk = s * 8 + kl;           // u32 index within 16-u32 row span
            uint32_t a[4][4], b[8][2];
#pragma unroll
            for (int ti = 0; ti < 4; ti++) {
                int m = amBase + ti * 16;
                a[ti][0] = As[m * RSTR + kk];
                a[ti][1] = As[(m + 8) * RSTR + kk];
                a[ti][2] = As[m * RSTR + kk + 4];
                a[ti][3] = As[(m + 8) * RSTR + kk + 4];
            }
#pragma unroll
            for (int tj = 0; tj < 8; tj++) {
                int n = bnBase + tj * 8;
                b[tj][0] = Bs[n * RSTR + kk];
                b[tj][1] = Bs[n * RSTR + kk + 4];
            }
#pragma unroll
            for (int ti = 0; ti < 4; ti++)
#pragma unroll
                for (int tj = 0; tj < 8; tj++)
                    mma_f16(c[ti][tj], a[ti], b[tj]);
        }
        __syncthreads();
    }

    // ---- epilogue
    int cm = m0 + (warp >> 1) * 64 + (lane >> 2);
    int cn = n0 + (warp & 1) * 64 + (lane & 3) * 2;
#pragma unroll
    for (int ti = 0; ti < 4; ti++) {
#pragma unroll
        for (int tj = 0; tj < 8; tj++) {
            float v0 = c[ti][tj][0], v1 = c[ti][tj][1];
            float v2 = c[ti][tj][2], v3 = c[ti][tj][3];
            if (GATHER) {   // phase 1: relu + fp16 store to g_hbuf_h
                __half2 h01 = __floats2half2_rn(fmaxf(v0, 0.f), fmaxf(v1, 0.f));
                __half2 h23 = __floats2half2_rn(fmaxf(v2, 0.f), fmaxf(v3, 0.f));
                size_t r0 = (size_t)(cm + ti * 16) * ldOut + cn + tj * 8;
                size_t r1 = (size_t)(cm + ti * 16 + 8) * ldOut + cn + tj * 8;
                *(__half2*)(g_hbuf_h + r0) = h01;
                *(__half2*)(g_hbuf_h + r1) = h23;
            } else {        // phase 2: fp32 store to g_ybuf
                size_t r0 = (size_t)(cm + ti * 16) * ldOut + cn + tj * 8;
                size_t r1 = (size_t)(cm + ti * 16 + 8) * ldOut + cn + tj * 8;
                *(float2*)(g_ybuf + r0) = make_float2(v0, v1);
                *(float2*)(g_ybuf + r1) = make_float2(v2, v3);
            }
        }
    }
}

// ---------------------------------------------------------------------------
// Kernel 7: combine — out[t] = w0 * ybuf[p0] + w1 * ybuf[p1]
// ---------------------------------------------------------------------------
__global__ void combine_kernel(float* __restrict__ out) {
    int t = blockIdx.x;
    int j = threadIdx.x * 4;
    int p0 = g_tok_pair[2 * t], p1 = g_tok_pair[2 * t + 1];
    float w0 = g_tok_w[2 * t], w1 = g_tok_w[2 * t + 1];
    float4 y0 = *(const float4*)(g_ybuf + (size_t)p0 * HDIM + j);
    float4 y1 = *(const float4*)(g_ybuf + (size_t)p1 * HDIM + j);
    float4 r;
    r.x = w0 * y0.x + w1 * y1.x;
    r.y = w0 * y0.y + w1 * y1.y;
    r.z = w0 * y0.z + w1 * y1.z;
    r.w = w0 * y0.w + w1 * y1.w;
    *(float4*)(out + (size_t)t * HDIM + j) = r;
}

// ---------------------------------------------------------------------------
// Launch — only harness pointers cross the host/device boundary
// ---------------------------------------------------------------------------
extern "C" void kernel_launch(void* const* d_in, const int* in_sizes, int n_in,
                              void* d_out, int out_size) {
    const float* x  = (const float*)d_in[0];
    const float* gw = (const float*)d_in[1];
    const float* w1 = (const float*)d_in[2];
    const float* w2 = (const float*)d_in[3];
    float* out = (float*)d_out;

    int write_logits = (out_size >= NT * HDIM + NT * NE) ? 1 : 0;

    reset_kernel<<<(MAXPAIR + 255) / 256, 256>>>();
    router_kernel<<<NT / 8, 256>>>(x, gw, out + (size_t)NT * HDIM, write_logits);
    scan_kernel<<<1, 1>>>();
    assign_kernel<<<(NT * TOPK + 255) / 256, 256>>>();

    // fp16 prep: x elementwise; w1/w2 transposed to [E][N][K]
    convert_x_kernel<<<592, 256>>>(x);
    transpose_h_kernel<1><<<dim3(FDIM / 32, HDIM / 32, NE), dim3(32, 8)>>>(
        w1, HDIM, FDIM);
    transpose_h_kernel<2><<<dim3(HDIM / 32, FDIM / 32, NE), dim3(32, 8)>>>(
        w2, FDIM, HDIM);

    // GEMM1: g_hbuf_h[p,:F] = relu(xh[tok(p),:H] @ w1h[e]^T)  (K=H, N/ldOut=F)
    moe_mma_f16_kernel<1><<<dim3(FDIM / BN, MTILES), 128>>>(HDIM, FDIM);
    // GEMM2: g_ybuf[p,:H] = hbuf_h[p,:F] @ w2h[e]^T           (K=F, N/ldOut=H)
    moe_mma_f16_kernel<0><<<dim3(HDIM / BN, MTILES), 128>>>(FDIM, HDIM);
    combine_kernel<<<NT, 256>>>(out);
}

// round 13
// speedup vs baseline: 1.9164x; 1.0598x over previous
#include <cuda_runtime.h>
#include <cuda_fp16.h>
#include <math.h>
#include <stdint.h>

// Shapes (fixed by reference)
#define NT    8192
#define HDIM  1024
#define FDIM  4096
#define NE    8
#define TOPK  2

// GEMM tiling: 128x128 CTA, 4 warps (64x64), KC=32 half, 2 stages, fp16 MMA
#define BM 128
#define BN 128
#define KC 32                    // halfs per chunk = 16 u32 per row
#define RSTR 20                  // u32 row stride: ldmatrix phases tile banks 0..31
#define TILE_U32 (BM * RSTR)     // 2560 u32 per tile (A or B)
#define ABYTES (TILE_U32 * 4)    // 10240
#define STAGE_U32 (2 * TILE_U32) // 5120
#define STAGE_BYTES (STAGE_U32 * 4)  // 20480; x2 stages = 40960 < 48K

#define MAXPAIR (NT * TOPK + NE * BM)   // 17408
#define MTILES  (MAXPAIR / BM)          // 136

// ---------------------------------------------------------------------------
// Scratch (device symbols: referenced ONLY from device code — host-side
// symbol args were the R7/R8 silent-zeros bug via GB300 ATS)
// ---------------------------------------------------------------------------
__device__ int    g_counts[NE];
__device__ int    g_cursor[NE];
__device__ int    g_seg[NE + 1];
__device__ int    g_pair_token[MAXPAIR];
__device__ int    g_tok_e[NT * TOPK];
__device__ float  g_tok_w[NT * TOPK];
__device__ int    g_tok_pair[NT * TOPK];
__device__ __half g_zrow_h[HDIM];                       // never written: zeros
__device__ __half g_xh [(size_t)NT * HDIM];             // fp16 x (written by router)
__device__ __half g_w1h[(size_t)NE * FDIM * HDIM];      // w1 as [E][F][H] fp16
__device__ __half g_w2h[(size_t)NE * HDIM * FDIM];      // w2 as [E][H][F] fp16
__device__ __half g_hbuf_h[(size_t)MAXPAIR * FDIM];     // relu(x@w1) fp16
__device__ float  g_ybuf[(size_t)MAXPAIR * HDIM];       // fp32 expert outputs

// ---------------------------------------------------------------------------
// PTX helpers (non-arch-specific: legal on compute_103)
// ---------------------------------------------------------------------------
__device__ __forceinline__ uint32_t smem_u32(const void* p) {
    uint32_t a;
    asm("{ .reg .u64 t; cvta.to.shared.u64 t, %1; cvt.u32.u64 %0, t; }"
        : "=r"(a) : "l"(p));
    return a;
}
__device__ __forceinline__ void cp16(uint32_t s, const void* g) {
    asm volatile("cp.async.cg.shared.global [%0], [%1], 16;"
                 :: "r"(s), "l"(g) : "memory");
}
__device__ __forceinline__ void cp_commit() {
    asm volatile("cp.async.commit_group;" ::: "memory");
}
__device__ __forceinline__ void cp_wait1() {
    asm volatile("cp.async.wait_group 1;" ::: "memory");
}
__device__ __forceinline__ void cp_wait0() {
    asm volatile("cp.async.wait_group 0;" ::: "memory");
}
__device__ __forceinline__ void ldsm4(uint32_t& d0, uint32_t& d1,
                                      uint32_t& d2, uint32_t& d3,
                                      uint32_t addr) {
    asm volatile("ldmatrix.sync.aligned.m8n8.x4.shared.b16 {%0,%1,%2,%3}, [%4];"
                 : "=r"(d0), "=r"(d1), "=r"(d2), "=r"(d3) : "r"(addr));
}
// fp16 MMA, fp32 accumulate: m16n8k16 (sm_80+, not arch-specific)
__device__ __forceinline__ void mma_f16(float* c, const uint32_t* a,
                                        const uint32_t* b) {
    asm volatile(
        "mma.sync.aligned.m16n8k16.row.col.f32.f16.f16.f32 "
        "{%0,%1,%2,%3}, {%4,%5,%6,%7}, {%8,%9}, {%0,%1,%2,%3};"
        : "+f"(c[0]), "+f"(c[1]), "+f"(c[2]), "+f"(c[3])
        : "r"(a[0]), "r"(a[1]), "r"(a[2]), "r"(a[3]), "r"(b[0]), "r"(b[1]));
}

// ---------------------------------------------------------------------------
// Kernel 0: reset per-launch state (graph replays reuse globals)
// ---------------------------------------------------------------------------
__global__ void reset_kernel() {
    int id = blockIdx.x * blockDim.x + threadIdx.x;
    if (id < MAXPAIR) g_pair_token[id] = -1;
    if (id < NE) { g_counts[id] = 0; g_cursor[id] = 0; }
}

// ---------------------------------------------------------------------------
// Kernel 1: router — exact fp32 logits + top-2; ALSO converts x -> g_xh fp16
// (fused: router already streams all of x)
// ---------------------------------------------------------------------------
__global__ void router_kernel(const float* __restrict__ x,
                              const float* __restrict__ gw,
                              float* __restrict__ logits_out,
                              int write_logits) {
    __shared__ float gwT[NE][HDIM];
    int tid = threadIdx.x;
    for (int idx = tid; idx < HDIM * NE; idx += 256) {
        int h = idx >> 3, e = idx & 7;
        gwT[e][h] = gw[idx];
    }
    __syncthreads();

    int warp = tid >> 5, lane = tid & 31;
    int t = blockIdx.x * 8 + warp;

    float acc[NE];
#pragma unroll
    for (int e = 0; e < NE; e++) acc[e] = 0.f;
    const float* xr = x + (size_t)t * HDIM;
    __half* xh = g_xh + (size_t)t * HDIM;
    for (int i = lane; i < HDIM; i += 32) {
        float xv = xr[i];
        xh[i] = __float2half_rn(xv);
#pragma unroll
        for (int e = 0; e < NE; e++) acc[e] += xv * gwT[e][i];
    }
#pragma unroll
    for (int e = 0; e < NE; e++)
        for (int off = 16; off; off >>= 1)
            acc[e] += __shfl_down_sync(0xffffffffu, acc[e], off);

    if (lane == 0) {
        if (write_logits) {
#pragma unroll
            for (int e = 0; e < NE; e++) logits_out[t * NE + e] = acc[e];
        }
        float l1 = -INFINITY, l2 = -INFINITY;
        int i1 = 0, i2 = 0;
#pragma unroll
        for (int e = 0; e < NE; e++) {
            float v = acc[e];
            if (v > l1)      { l2 = l1; i2 = i1; l1 = v; i1 = e; }
            else if (v > l2) { l2 = v; i2 = e; }
        }
        float b = expf(l2 - l1);
        float s = 1.f + b;
        g_tok_e[2 * t] = i1;  g_tok_e[2 * t + 1] = i2;
        g_tok_w[2 * t] = 1.f / s;
        g_tok_w[2 * t + 1] = b / s;
        atomicAdd(&g_counts[i1], 1);
        atomicAdd(&g_counts[i2], 1);
    }
}

__global__ void scan_kernel() {
    int s = 0;
    for (int e = 0; e < NE; e++) {
        g_seg[e] = s;
        s += ((g_counts[e] + BM - 1) / BM) * BM;
    }
    g_seg[NE] = s;
}

__global__ void assign_kernel() {
    int id = blockIdx.x * blockDim.x + threadIdx.x;
    if (id >= NT * TOPK) return;
    int e = g_tok_e[id];
    int pos = atomicAdd(&g_cursor[e], 1);
    int p = g_seg[e] + pos;
    g_pair_token[p] = id >> 1;
    g_tok_pair[id] = p;
}

// ---------------------------------------------------------------------------
// Kernel 2: transpose + convert weights: src [E][R][C] f32 -> dst [E][C][R] fp16
// ---------------------------------------------------------------------------
template <int DST>
__global__ void transpose_h_kernel(const float* __restrict__ src, int R, int C) {
    __shared__ float tile[32][33];
    __half* dstB = (DST == 1) ? g_w1h : g_w2h;
    int e = blockIdx.z;
    int c0 = blockIdx.x * 32, r0 = blockIdx.y * 32;
    const float* s = src + (size_t)e * R * C;
    __half* d = dstB + (size_t)e * R * C;
    int tx = threadIdx.x, ty = threadIdx.y;   // 32 x 8
#pragma unroll
    for (int i = 0; i < 32; i += 8)
        tile[ty + i][tx] = s[(size_t)(r0 + ty + i) * C + c0 + tx];
    __syncthreads();
#pragma unroll
    for (int i = 0; i < 32; i += 8)
        d[(size_t)(c0 + ty + i) * R + r0 + tx] = __float2half_rn(tile[tx][ty + i]);
}

// ---------------------------------------------------------------------------
// Kernel 3: fp16 mma.sync GEMM with ldmatrix fragment loads.
//   D[m,n] = A[m,:K] @ B[n,:K]^T ; A,B both stored row-major-by-K in smem.
//   PHASE1 (GATHER=1): A = g_xh via g_pair_token, B = g_w1h -> g_hbuf_h (+relu)
//   PHASE2 (GATHER=0): A = g_hbuf_h,              B = g_w2h -> g_ybuf (f32)
// ---------------------------------------------------------------------------
template <int GATHER>
__global__ __launch_bounds__(128, 2)
void moe_mma_f16_kernel(int K, int ldOut) {
    __shared__ uint32_t sm[2 * STAGE_U32];

    const __half* Abase = GATHER ? g_xh : g_hbuf_h;
    const __half* Bbase = GATHER ? g_w1h : g_w2h;

    int m0 = blockIdx.y * BM;
    if (m0 >= g_seg[NE]) return;
    int n0 = blockIdx.x * BN;

    int e = 0;
#pragma unroll
    for (int i = 1; i < NE; i++) if (m0 >= g_seg[i]) e = i;
    const __half* Bexp = Bbase + (size_t)e * (size_t)ldOut * K;  // [N][K]

    int tid = threadIdx.x;
    int warp = tid >> 5, lane = tid & 31;
    int warpM = warp >> 1, warpN = warp & 1;

    // global-load mapping: thread t owns A row t and B row (n0+t): 32 half = 4 cp16
    const __half* aG;
    if (GATHER) {
        int tk = g_pair_token[m0 + tid];
        aG = (tk >= 0) ? (Abase + (size_t)tk * K) : g_zrow_h;
    } else {
        aG = Abase + (size_t)(m0 + tid) * K;
    }
    const __half* bG = Bexp + (size_t)(n0 + tid) * K;

    uint32_t sbase = smem_u32(sm);
    uint32_t aS = sbase + (uint32_t)(tid * RSTR) * 4u;
    uint32_t bS = sbase + (uint32_t)ABYTES + (uint32_t)(tid * RSTR) * 4u;

    // ldmatrix per-lane byte offsets (relative to tile base)
    //  A: row = warpM*64 + (lane&15) [+ ti*16], k-u32 offset (lane>>4)*4
    uint32_t aRowOff = (uint32_t)(((warpM * 64 + (lane & 15)) * RSTR +
                                   ((lane >> 4) << 2)) * 4);
    //  B: row n = warpN*64 + (lane&7) + (lane>>4)*8 [+ tjp*16],
    //     k-u32 offset ((lane>>3)&1)*4
    uint32_t bRowOff = (uint32_t)(((warpN * 64 + (lane & 7) + (lane >> 4) * 8) * RSTR +
                                   (((lane >> 3) & 1) << 2)) * 4);

    const int NC = K / KC;

    float c[4][8][4];
#pragma unroll
    for (int ti = 0; ti < 4; ti++)
#pragma unroll
        for (int tj = 0; tj < 8; tj++)
#pragma unroll
            for (int q = 0; q < 4; q++) c[ti][tj][q] = 0.f;

    // ---- prologue: chunk 0
#pragma unroll
    for (int j = 0; j < 4; j++) cp16(aS + j * 16, aG + j * 8);
#pragma unroll
    for (int j = 0; j < 4; j++) cp16(bS + j * 16, bG + j * 8);
    cp_commit();

    for (int i = 0; i < NC; i++) {
        if (i + 1 < NC) {
            uint32_t so = (uint32_t)(((i + 1) & 1) * STAGE_BYTES);
            size_t ko = (size_t)(i + 1) * KC;
#pragma unroll
            for (int j = 0; j < 4; j++) cp16(aS + so + j * 16, aG + ko + j * 8);
#pragma unroll
            for (int j = 0; j < 4; j++) cp16(bS + so + j * 16, bG + ko + j * 8);
            cp_commit();
            cp_wait1();
        } else {
            cp_wait0();
        }
        __syncthreads();

        uint32_t stA = sbase + (uint32_t)((i & 1) * STAGE_BYTES);
        uint32_t stB = stA + (uint32_t)ABYTES;

        // 2 k16-steps per chunk (KC=32 half; step s -> +s*32 bytes = 8 u32)
#pragma unroll
        for (int s = 0; s < 2; s++) {
            uint32_t kOfs = (uint32_t)(s * 32);
            uint32_t a[4][4], b[8][2];
#pragma unroll
            for (int ti = 0; ti < 4; ti++) {
                ldsm4(a[ti][0], a[ti][1], a[ti][2], a[ti][3],
                      stA + aRowOff + (uint32_t)(ti * 16 * RSTR * 4) + kOfs);
            }
#pragma unroll
            for (int tjp = 0; tjp < 4; tjp++) {
                ldsm4(b[2 * tjp][0], b[2 * tjp][1],
                      b[2 * tjp + 1][0], b[2 * tjp + 1][1],
                      stB + bRowOff + (uint32_t)(tjp * 16 * RSTR * 4) + kOfs);
            }
#pragma unroll
            for (int ti = 0; ti < 4; ti++)
#pragma unroll
                for (int tj = 0; tj < 8; tj++)
                    mma_f16(c[ti][tj], a[ti], b[tj]);
        }
        __syncthreads();
    }

    // ---- epilogue
    int cm = m0 + warpM * 64 + (lane >> 2);
    int cn = n0 + warpN * 64 + (lane & 3) * 2;
#pragma unroll
    for (int ti = 0; ti < 4; ti++) {
#pragma unroll
        for (int tj = 0; tj < 8; tj++) {
            float v0 = c[ti][tj][0], v1 = c[ti][tj][1];
            float v2 = c[ti][tj][2], v3 = c[ti][tj][3];
            if (GATHER) {   // phase 1: relu + fp16 store
                __half2 h01 = __floats2half2_rn(fmaxf(v0, 0.f), fmaxf(v1, 0.f));
                __half2 h23 = __floats2half2_rn(fmaxf(v2, 0.f), fmaxf(v3, 0.f));
                size_t r0 = (size_t)(cm + ti * 16) * ldOut + cn + tj * 8;
                size_t r1 = (size_t)(cm + ti * 16 + 8) * ldOut + cn + tj * 8;
                *(__half2*)(g_hbuf_h + r0) = h01;
                *(__half2*)(g_hbuf_h + r1) = h23;
            } else {        // phase 2: fp32 store
                size_t r0 = (size_t)(cm + ti * 16) * ldOut + cn + tj * 8;
                size_t r1 = (size_t)(cm + ti * 16 + 8) * ldOut + cn + tj * 8;
                *(float2*)(g_ybuf + r0) = make_float2(v0, v1);
                *(float2*)(g_ybuf + r1) = make_float2(v2, v3);
            }
        }
    }
}

// ---------------------------------------------------------------------------
// Kernel 4: combine — out[t] = w0 * ybuf[p0] + w1 * ybuf[p1]
// ---------------------------------------------------------------------------
__global__ void combine_kernel(float* __restrict__ out) {
    int t = blockIdx.x;
    int j = threadIdx.x * 4;
    int p0 = g_tok_pair[2 * t], p1 = g_tok_pair[2 * t + 1];
    float w0 = g_tok_w[2 * t], w1 = g_tok_w[2 * t + 1];
    float4 y0 = *(const float4*)(g_ybuf + (size_t)p0 * HDIM + j);
    float4 y1 = *(const float4*)(g_ybuf + (size_t)p1 * HDIM + j);
    float4 r;
    r.x = w0 * y0.x + w1 * y1.x;
    r.y = w0 * y0.y + w1 * y1.y;
    r.z = w0 * y0.z + w1 * y1.z;
    r.w = w0 * y0.w + w1 * y1.w;
    *(float4*)(out + (size_t)t * HDIM + j) = r;
}

// ---------------------------------------------------------------------------
// Launch — only harness pointers cross the host/device boundary
// ---------------------------------------------------------------------------
extern "C" void kernel_launch(void* const* d_in, const int* in_sizes, int n_in,
                              void* d_out, int out_size) {
    const float* x  = (const float*)d_in[0];
    const float* gw = (const float*)d_in[1];
    const float* w1 = (const float*)d_in[2];
    const float* w2 = (const float*)d_in[3];
    float* out = (float*)d_out;

    int write_logits = (out_size >= NT * HDIM + NT * NE) ? 1 : 0;

    reset_kernel<<<(MAXPAIR + 255) / 256, 256>>>();
    router_kernel<<<NT / 8, 256>>>(x, gw, out + (size_t)NT * HDIM, write_logits);
    scan_kernel<<<1, 1>>>();
    assign_kernel<<<(NT * TOPK + 255) / 256, 256>>>();

    // fp16 weight prep: transpose to [E][N][K]
    transpose_h_kernel<1><<<dim3(FDIM / 32, HDIM / 32, NE), dim3(32, 8)>>>(
        w1, HDIM, FDIM);
    transpose_h_kernel<2><<<dim3(HDIM / 32, FDIM / 32, NE), dim3(32, 8)>>>(
        w2, FDIM, HDIM);

    // GEMM1: g_hbuf_h[p,:F] = relu(xh[tok(p),:H] @ w1h[e]^T)  (K=H, ldOut=F)
    moe_mma_f16_kernel<1><<<dim3(FDIM / BN, MTILES), 128>>>(HDIM, FDIM);
    // GEMM2: g_ybuf[p,:H] = hbuf_h[p,:F] @ w2h[e]^T           (K=F, ldOut=H)
    moe_mma_f16_kernel<0><<<dim3(HDIM / BN, MTILES), 128>>>(FDIM, HDIM);
    combine_kernel<<<NT, 256>>>(out);
}

// round 15
// speedup vs baseline: 1.9566x; 1.0210x over previous
#include <cuda_runtime.h>
#include <cuda_fp16.h>
#include <math.h>
#include <stdint.h>

// Shapes (fixed by reference)
#define NT    8192
#define HDIM  1024
#define FDIM  4096
#define NE    8
#define TOPK  2

// GEMM tiling: 128x128 CTA, 4 warps (64x64), KC=32 half, fp16 MMA
#define BM 128
#define BN 128
#define KC 32                    // halfs per chunk = 16 u32 per row
#define RSTR 20                  // u32 row stride: ldmatrix phases tile banks 0..31
#define TILE_U32 (BM * RSTR)     // 2560 u32 per tile (A or B)
#define ABYTES (TILE_U32 * 4)    // 10240
#define STAGE_U32 (2 * TILE_U32) // 5120
#define STAGE_BYTES (STAGE_U32 * 4)  // 20480
#define SMEM_P3 (3 * STAGE_BYTES)    // 61440 (dynamic, opt-in; 2 CTA = 122880)

#define MAXPAIR (NT * TOPK + NE * BM)   // 17408
#define MTILES  (MAXPAIR / BM)          // 136

// ---------------------------------------------------------------------------
// Scratch (device symbols: referenced ONLY from device code — host-side
// symbol args were the R7/R8 silent-zeros bug via GB300 ATS)
// ---------------------------------------------------------------------------
__device__ int    g_counts[NE];
__device__ int    g_cursor[NE];
__device__ int    g_seg[NE + 1];
__device__ int    g_pair_token[MAXPAIR];
__device__ int    g_tok_e[NT * TOPK];
__device__ float  g_tok_w[NT * TOPK];
__device__ int    g_tok_pair[NT * TOPK];
__device__ __half g_zrow_h[HDIM];                       // never written: zeros
__device__ __half g_xh [(size_t)NT * HDIM];             // fp16 x (router writes)
__device__ __half g_w1h[(size_t)NE * FDIM * HDIM];      // w1 as [E][F][H] fp16
__device__ __half g_w2h[(size_t)NE * HDIM * FDIM];      // w2 as [E][H][F] fp16
__device__ __half g_hbuf_h[(size_t)MAXPAIR * FDIM];     // relu(x@w1) fp16
__device__ float  g_ybuf[(size_t)MAXPAIR * HDIM];       // fp32 expert outputs

// ---------------------------------------------------------------------------
// PTX helpers (non-arch-specific: legal on compute_103)
// ---------------------------------------------------------------------------
__device__ __forceinline__ uint32_t smem_u32(const void* p) {
    uint32_t a;
    asm("{ .reg .u64 t; cvta.to.shared.u64 t, %1; cvt.u32.u64 %0, t; }"
        : "=r"(a) : "l"(p));
    return a;
}
__device__ __forceinline__ void cp16(uint32_t s, const void* g) {
    asm volatile("cp.async.cg.shared.global [%0], [%1], 16;"
                 :: "r"(s), "l"(g) : "memory");
}
__device__ __forceinline__ void cp_commit() {
    asm volatile("cp.async.commit_group;" ::: "memory");
}
__device__ __forceinline__ void cp_wait1() {
    asm volatile("cp.async.wait_group 1;" ::: "memory");
}
__device__ __forceinline__ void cp_wait0() {
    asm volatile("cp.async.wait_group 0;" ::: "memory");
}
__device__ __forceinline__ void ldsm4(uint32_t& d0, uint32_t& d1,
                                      uint32_t& d2, uint32_t& d3,
                                      uint32_t addr) {
    asm volatile("ldmatrix.sync.aligned.m8n8.x4.shared.b16 {%0,%1,%2,%3}, [%4];"
                 : "=r"(d0), "=r"(d1), "=r"(d2), "=r"(d3) : "r"(addr));
}
__device__ __forceinline__ void mma_f16(float* c, const uint32_t* a,
                                        const uint32_t* b) {
    asm volatile(
        "mma.sync.aligned.m16n8k16.row.col.f32.f16.f16.f32 "
        "{%0,%1,%2,%3}, {%4,%5,%6,%7}, {%8,%9}, {%0,%1,%2,%3};"
        : "+f"(c[0]), "+f"(c[1]), "+f"(c[2]), "+f"(c[3])
        : "r"(a[0]), "r"(a[1]), "r"(a[2]), "r"(a[3]), "r"(b[0]), "r"(b[1]));
}

// ---------------------------------------------------------------------------
// Kernel 0: reset per-launch state (graph replays reuse globals)
// ---------------------------------------------------------------------------
__global__ void reset_kernel() {
    int id = blockIdx.x * blockDim.x + threadIdx.x;
    if (id < MAXPAIR) g_pair_token[id] = -1;
    if (id < NE) { g_counts[id] = 0; g_cursor[id] = 0; }
}

// ---------------------------------------------------------------------------
// Kernel 1: router — exact fp32 logits + top-2; also converts x -> g_xh fp16
// ---------------------------------------------------------------------------
__global__ void router_kernel(const float* __restrict__ x,
                              const float* __restrict__ gw,
                              float* __restrict__ logits_out,
                              int write_logits) {
    __shared__ float gwT[NE][HDIM];
    int tid = threadIdx.x;
    for (int idx = tid; idx < HDIM * NE; idx += 256) {
        int h = idx >> 3, e = idx & 7;
        gwT[e][h] = gw[idx];
    }
    __syncthreads();

    int warp = tid >> 5, lane = tid & 31;
    int t = blockIdx.x * 8 + warp;

    float acc[NE];
#pragma unroll
    for (int e = 0; e < NE; e++) acc[e] = 0.f;
    const float* xr = x + (size_t)t * HDIM;
    __half* xh = g_xh + (size_t)t * HDIM;
    for (int i = lane; i < HDIM; i += 32) {
        float xv = xr[i];
        xh[i] = __float2half_rn(xv);
#pragma unroll
        for (int e = 0; e < NE; e++) acc[e] += xv * gwT[e][i];
    }
#pragma unroll
    for (int e = 0; e < NE; e++)
        for (int off = 16; off; off >>= 1)
            acc[e] += __shfl_down_sync(0xffffffffu, acc[e], off);

    if (lane == 0) {
        if (write_logits) {
#pragma unroll
            for (int e = 0; e < NE; e++) logits_out[t * NE + e] = acc[e];
        }
        float l1 = -INFINITY, l2 = -INFINITY;
        int i1 = 0, i2 = 0;
#pragma unroll
        for (int e = 0; e < NE; e++) {
            float v = acc[e];
            if (v > l1)      { l2 = l1; i2 = i1; l1 = v; i1 = e; }
            else if (v > l2) { l2 = v; i2 = e; }
        }
        float b = expf(l2 - l1);
        float s = 1.f + b;
        g_tok_e[2 * t] = i1;  g_tok_e[2 * t + 1] = i2;
        g_tok_w[2 * t] = 1.f / s;
        g_tok_w[2 * t + 1] = b / s;
        atomicAdd(&g_counts[i1], 1);
        atomicAdd(&g_counts[i2], 1);
    }
}

__global__ void scan_kernel() {
    int s = 0;
    for (int e = 0; e < NE; e++) {
        g_seg[e] = s;
        s += ((g_counts[e] + BM - 1) / BM) * BM;
    }
    g_seg[NE] = s;
}

__global__ void assign_kernel() {
    int id = blockIdx.x * blockDim.x + threadIdx.x;
    if (id >= NT * TOPK) return;
    int e = g_tok_e[id];
    int pos = atomicAdd(&g_cursor[e], 1);
    int p = g_seg[e] + pos;
    g_pair_token[p] = id >> 1;
    g_tok_pair[id] = p;
}

// ---------------------------------------------------------------------------
// Kernel 2: transpose + convert weights: src [E][R][C] f32 -> dst [E][C][R] fp16
// ---------------------------------------------------------------------------
template <int DST>
__global__ void transpose_h_kernel(const float* __restrict__ src, int R, int C) {
    __shared__ float tile[32][33];
    __half* dstB = (DST == 1) ? g_w1h : g_w2h;
    int e = blockIdx.z;
    int c0 = blockIdx.x * 32, r0 = blockIdx.y * 32;
    const float* s = src + (size_t)e * R * C;
    __half* d = dstB + (size_t)e * R * C;
    int tx = threadIdx.x, ty = threadIdx.y;   // 32 x 8
#pragma unroll
    for (int i = 0; i < 32; i += 8)
        tile[ty + i][tx] = s[(size_t)(r0 + ty + i) * C + c0 + tx];
    __syncthreads();
#pragma unroll
    for (int i = 0; i < 32; i += 8)
        d[(size_t)(c0 + ty + i) * R + r0 + tx] = __float2half_rn(tile[tx][ty + i]);
}

// ---------------------------------------------------------------------------
// Shared GEMM body pieces (both variants): fragment addressing + epilogue
// are identical; only the pipeline differs.
// ---------------------------------------------------------------------------

// 3-STAGE variant: dynamic smem, ONE barrier per chunk (stage written at
// iter i is the stage of chunk i-1, already protected by the pre-compute
// barrier). Prefetch distance 2.
template <int GATHER>
__global__ __launch_bounds__(128, 2)
void moe_mma_f16_p3(int K, int ldOut) {
    extern __shared__ uint32_t smd[];

    const __half* Abase = GATHER ? g_xh : g_hbuf_h;
    const __half* Bbase = GATHER ? g_w1h : g_w2h;

    int m0 = blockIdx.y * BM;
    if (m0 >= g_seg[NE]) return;
    int n0 = blockIdx.x * BN;

    int e = 0;
#pragma unroll
    for (int i = 1; i < NE; i++) if (m0 >= g_seg[i]) e = i;
    const __half* Bexp = Bbase + (size_t)e * (size_t)ldOut * K;  // [N][K]

    int tid = threadIdx.x;
    int warp = tid >> 5, lane = tid & 31;
    int warpM = warp >> 1, warpN = warp & 1;

    const __half* aG;
    if (GATHER) {
        int tk = g_pair_token[m0 + tid];
        aG = (tk >= 0) ? (Abase + (size_t)tk * K) : g_zrow_h;
    } else {
        aG = Abase + (size_t)(m0 + tid) * K;
    }
    const __half* bG = Bexp + (size_t)(n0 + tid) * K;

    uint32_t sbase = smem_u32(smd);
    uint32_t aS = sbase + (uint32_t)(tid * RSTR) * 4u;
    uint32_t bS = sbase + (uint32_t)ABYTES + (uint32_t)(tid * RSTR) * 4u;

    uint32_t aRowOff = (uint32_t)(((warpM * 64 + (lane & 15)) * RSTR +
                                   ((lane >> 4) << 2)) * 4);
    uint32_t bRowOff = (uint32_t)(((warpN * 64 + (lane & 7) + (lane >> 4) * 8) * RSTR +
                                   (((lane >> 3) & 1) << 2)) * 4);

    const int NC = K / KC;

    float c[4][8][4];
#pragma unroll
    for (int ti = 0; ti < 4; ti++)
#pragma unroll
        for (int tj = 0; tj < 8; tj++)
#pragma unroll
            for (int q = 0; q < 4; q++) c[ti][tj][q] = 0.f;

    // ---- prologue: chunks 0,1 into stages 0,1
#pragma unroll
    for (int ch = 0; ch < 2; ch++) {
        uint32_t so = (uint32_t)(ch * STAGE_BYTES);
        size_t ko = (size_t)ch * KC;
#pragma unroll
        for (int j = 0; j < 4; j++) cp16(aS + so + j * 16, aG + ko + j * 8);
#pragma unroll
        for (int j = 0; j < 4; j++) cp16(bS + so + j * 16, bG + ko + j * 8);
        cp_commit();
    }

    int stage = 0;   // stage of chunk i
    for (int i = 0; i < NC; i++) {
        if (i + 1 < NC) cp_wait1(); else cp_wait0();
        __syncthreads();                       // the ONLY barrier per chunk

        if (i + 2 < NC) {                      // prefetch chunk i+2
            int ws = stage + 2; if (ws >= 3) ws -= 3;
            uint32_t so = (uint32_t)(ws * STAGE_BYTES);
            size_t ko = (size_t)(i + 2) * KC;
#pragma unroll
            for (int j = 0; j < 4; j++) cp16(aS + so + j * 16, aG + ko + j * 8);
#pragma unroll
            for (int j = 0; j < 4; j++) cp16(bS + so + j * 16, bG + ko + j * 8);
            cp_commit();
        }

        uint32_t stA = sbase + (uint32_t)(stage * STAGE_BYTES);
        uint32_t stB = stA + (uint32_t)ABYTES;

#pragma unroll
        for (int s = 0; s < 2; s++) {
            uint32_t kOfs = (uint32_t)(s * 32);
            uint32_t a[4][4], b[8][2];
#pragma unroll
            for (int ti = 0; ti < 4; ti++)
                ldsm4(a[ti][0], a[ti][1], a[ti][2], a[ti][3],
                      stA + aRowOff + (uint32_t)(ti * 16 * RSTR * 4) + kOfs);
#pragma unroll
            for (int tjp = 0; tjp < 4; tjp++)
                ldsm4(b[2 * tjp][0], b[2 * tjp][1],
                      b[2 * tjp + 1][0], b[2 * tjp + 1][1],
                      stB + bRowOff + (uint32_t)(tjp * 16 * RSTR * 4) + kOfs);
#pragma unroll
            for (int ti = 0; ti < 4; ti++)
#pragma unroll
                for (int tj = 0; tj < 8; tj++)
                    mma_f16(c[ti][tj], a[ti], b[tj]);
        }
        if (++stage == 3) stage = 0;
    }

    // ---- epilogue
    int cm = m0 + warpM * 64 + (lane >> 2);
    int cn = n0 + warpN * 64 + (lane & 3) * 2;
#pragma unroll
    for (int ti = 0; ti < 4; ti++) {
#pragma unroll
        for (int tj = 0; tj < 8; tj++) {
            float v0 = c[ti][tj][0], v1 = c[ti][tj][1];
            float v2 = c[ti][tj][2], v3 = c[ti][tj][3];
            if (GATHER) {
                __half2 h01 = __floats2half2_rn(fmaxf(v0, 0.f), fmaxf(v1, 0.f));
                __half2 h23 = __floats2half2_rn(fmaxf(v2, 0.f), fmaxf(v3, 0.f));
                size_t r0 = (size_t)(cm + ti * 16) * ldOut + cn + tj * 8;
                size_t r1 = (size_t)(cm + ti * 16 + 8) * ldOut + cn + tj * 8;
                *(__half2*)(g_hbuf_h + r0) = h01;
                *(__half2*)(g_hbuf_h + r1) = h23;
            } else {
                size_t r0 = (size_t)(cm + ti * 16) * ldOut + cn + tj * 8;
                size_t r1 = (size_t)(cm + ti * 16 + 8) * ldOut + cn + tj * 8;
                *(float2*)(g_ybuf + r0) = make_float2(v0, v1);
                *(float2*)(g_ybuf + r1) = make_float2(v2, v3);
            }
        }
    }
}

// 2-STAGE fallback: the exact R13 kernel (static smem, cannot be rejected)
template <int GATHER>
__global__ __launch_bounds__(128, 2)
void moe_mma_f16_p2(int K, int ldOut) {
    __shared__ uint32_t sm[2 * STAGE_U32];

    const __half* Abase = GATHER ? g_xh : g_hbuf_h;
    const __half* Bbase = GATHER ? g_w1h : g_w2h;

    int m0 = blockIdx.y * BM;
    if (m0 >= g_seg[NE]) return;
    int n0 = blockIdx.x * BN;

    int e = 0;
#pragma unroll
    for (int i = 1; i < NE; i++) if (m0 >= g_seg[i]) e = i;
    const __half* Bexp = Bbase + (size_t)e * (size_t)ldOut * K;

    int tid = threadIdx.x;
    int warp = tid >> 5, lane = tid & 31;
    int warpM = warp >> 1, warpN = warp & 1;

    const __half* aG;
    if (GATHER) {
        int tk = g_pair_token[m0 + tid];
        aG = (tk >= 0) ? (Abase + (size_t)tk * K) : g_zrow_h;
    } else {
        aG = Abase + (size_t)(m0 + tid) * K;
    }
    const __half* bG = Bexp + (size_t)(n0 + tid) * K;

    uint32_t sbase = smem_u32(sm);
    uint32_t aS = sbase + (uint32_t)(tid * RSTR) * 4u;
    uint32_t bS = sbase + (uint32_t)ABYTES + (uint32_t)(tid * RSTR) * 4u;

    uint32_t aRowOff = (uint32_t)(((warpM * 64 + (lane & 15)) * RSTR +
                                   ((lane >> 4) << 2)) * 4);
    uint32_t bRowOff = (uint32_t)(((warpN * 64 + (lane & 7) + (lane >> 4) * 8) * RSTR +
                                   (((lane >> 3) & 1) << 2)) * 4);

    const int NC = K / KC;

    float c[4][8][4];
#pragma unroll
    for (int ti = 0; ti < 4; ti++)
#pragma unroll
        for (int tj = 0; tj < 8; tj++)
#pragma unroll
            for (int q = 0; q < 4; q++) c[ti][tj][q] = 0.f;

#pragma unroll
    for (int j = 0; j < 4; j++) cp16(aS + j * 16, aG + j * 8);
#pragma unroll
    for (int j = 0; j < 4; j++) cp16(bS + j * 16, bG + j * 8);
    cp_commit();

    for (int i = 0; i < NC; i++) {
        if (i + 1 < NC) {
            uint32_t so = (uint32_t)(((i + 1) & 1) * STAGE_BYTES);
            size_t ko = (size_t)(i + 1) * KC;
#pragma unroll
            for (int j = 0; j < 4; j++) cp16(aS + so + j * 16, aG + ko + j * 8);
#pragma unroll
            for (int j = 0; j < 4; j++) cp16(bS + so + j * 16, bG + ko + j * 8);
            cp_commit();
            cp_wait1();
        } else {
            cp_wait0();
        }
        __syncthreads();

        uint32_t stA = sbase + (uint32_t)((i & 1) * STAGE_BYTES);
        uint32_t stB = stA + (uint32_t)ABYTES;

#pragma unroll
        for (int s = 0; s < 2; s++) {
            uint32_t kOfs = (uint32_t)(s * 32);
            uint32_t a[4][4], b[8][2];
#pragma unroll
            for (int ti = 0; ti < 4; ti++)
                ldsm4(a[ti][0], a[ti][1], a[ti][2], a[ti][3],
                      stA + aRowOff + (uint32_t)(ti * 16 * RSTR * 4) + kOfs);
#pragma unroll
            for (int tjp = 0; tjp < 4; tjp++)
                ldsm4(b[2 * tjp][0], b[2 * tjp][1],
                      b[2 * tjp + 1][0], b[2 * tjp + 1][1],
                      stB + bRowOff + (uint32_t)(tjp * 16 * RSTR * 4) + kOfs);
#pragma unroll
            for (int ti = 0; ti < 4; ti++)
#pragma unroll
                for (int tj = 0; tj < 8; tj++)
                    mma_f16(c[ti][tj], a[ti], b[tj]);
        }
        __syncthreads();
    }

    int cm = m0 + warpM * 64 + (lane >> 2);
    int cn = n0 + warpN * 64 + (lane & 3) * 2;
#pragma unroll
    for (int ti = 0; ti < 4; ti++) {
#pragma unroll
        for (int tj = 0; tj < 8; tj++) {
            float v0 = c[ti][tj][0], v1 = c[ti][tj][1];
            float v2 = c[ti][tj][2], v3 = c[ti][tj][3];
            if (GATHER) {
                __half2 h01 = __floats2half2_rn(fmaxf(v0, 0.f), fmaxf(v1, 0.f));
                __half2 h23 = __floats2half2_rn(fmaxf(v2, 0.f), fmaxf(v3, 0.f));
                size_t r0 = (size_t)(cm + ti * 16) * ldOut + cn + tj * 8;
                size_t r1 = (size_t)(cm + ti * 16 + 8) * ldOut + cn + tj * 8;
                *(__half2*)(g_hbuf_h + r0) = h01;
                *(__half2*)(g_hbuf_h + r1) = h23;
            } else {
                size_t r0 = (size_t)(cm + ti * 16) * ldOut + cn + tj * 8;
                size_t r1 = (size_t)(cm + ti * 16 + 8) * ldOut + cn + tj * 8;
                *(float2*)(g_ybuf + r0) = make_float2(v0, v1);
                *(float2*)(g_ybuf + r1) = make_float2(v2, v3);
            }
        }
    }
}

// ---------------------------------------------------------------------------
// Kernel: combine — out[t] = w0 * ybuf[p0] + w1 * ybuf[p1]
// ---------------------------------------------------------------------------
__global__ void combine_kernel(float* __restrict__ out) {
    int t = blockIdx.x;
    int j = threadIdx.x * 4;
    int p0 = g_tok_pair[2 * t], p1 = g_tok_pair[2 * t + 1];
    float w0 = g_tok_w[2 * t], w1 = g_tok_w[2 * t + 1];
    float4 y0 = *(const float4*)(g_ybuf + (size_t)p0 * HDIM + j);
    float4 y1 = *(const float4*)(g_ybuf + (size_t)p1 * HDIM + j);
    float4 r;
    r.x = w0 * y0.x + w1 * y1.x;
    r.y = w0 * y0.y + w1 * y1.y;
    r.z = w0 * y0.z + w1 * y1.z;
    r.w = w0 * y0.w + w1 * y1.w;
    *(float4*)(out + (size_t)t * HDIM + j) = r;
}

// ---------------------------------------------------------------------------
// Launch — only harness pointers cross the host/device boundary; 3-stage
// path gated on VERIFIED smem opt-in, else exact R13 fallback.
// ---------------------------------------------------------------------------
extern "C" void kernel_launch(void* const* d_in, const int* in_sizes, int n_in,
                              void* d_out, int out_size) {
    const float* x  = (const float*)d_in[0];
    const float* gw = (const float*)d_in[1];
    const float* w1 = (const float*)d_in[2];
    const float* w2 = (const float*)d_in[3];
    float* out = (float*)d_out;

    int write_logits = (out_size >= NT * HDIM + NT * NE) ? 1 : 0;

    cudaError_t e1 = cudaFuncSetAttribute(
        (const void*)moe_mma_f16_p3<1>,
        cudaFuncAttributeMaxDynamicSharedMemorySize, SMEM_P3);
    cudaError_t e2 = cudaFuncSetAttribute(
        (const void*)moe_mma_f16_p3<0>,
        cudaFuncAttributeMaxDynamicSharedMemorySize, SMEM_P3);
    bool p3 = (e1 == cudaSuccess && e2 == cudaSuccess);

    reset_kernel<<<(MAXPAIR + 255) / 256, 256>>>();
    router_kernel<<<NT / 8, 256>>>(x, gw, out + (size_t)NT * HDIM, write_logits);
    scan_kernel<<<1, 1>>>();
    assign_kernel<<<(NT * TOPK + 255) / 256, 256>>>();

    transpose_h_kernel<1><<<dim3(FDIM / 32, HDIM / 32, NE), dim3(32, 8)>>>(
        w1, HDIM, FDIM);
    transpose_h_kernel<2><<<dim3(HDIM / 32, FDIM / 32, NE), dim3(32, 8)>>>(
        w2, FDIM, HDIM);

    if (p3) {
        moe_mma_f16_p3<1><<<dim3(FDIM / BN, MTILES), 128, SMEM_P3>>>(HDIM, FDIM);
        moe_mma_f16_p3<0><<<dim3(HDIM / BN, MTILES), 128, SMEM_P3>>>(FDIM, HDIM);
    } else {
        moe_mma_f16_p2<1><<<dim3(FDIM / BN, MTILES), 128>>>(HDIM, FDIM);
        moe_mma_f16_p2<0><<<dim3(HDIM / BN, MTILES), 128>>>(FDIM, HDIM);
    }
    combine_kernel<<<NT, 256>>>(out);
}